// round 10
// baseline (speedup 1.0000x reference)
#include <cuda_runtime.h>
#include <cuda_fp16.h>
#include <cstdint>

// ImplicitFunction: fp16 m16n8k16 mma.sync, 2-term static weight split
// (W*s = Whi + Wlo), dynamically range-scaled fp16 activations.
// Round-10: scale s folded into weights at prep; tree-max + redux.sync +
// rcp.approx quantize; and per warp TWO pipelined 16-row chains scheduled
// mmaA(l) -> epiB(l-1) -> mmaB(l) -> epiA(l) so each epilogue overlaps the
// other chain's HMMA drain.

#define NT 256
#define TILE_M 256          // 8 warps * 2 chains * 16 rows
#define NEG 0.2f
#define NLAYER 6

#define OFF_WF   0
#define WF_BYTES (NLAYER * 8 * 4 * 32 * 16)   // [l][nt][kt][lane]{hi0,hi1,lo0,lo1}
#define OFF_BH   (OFF_WF + WF_BYTES)
#define OFF_W0   (OFF_BH + 1536)
#define OFF_S0   (OFF_W0 + 768)
#define OFF_B0   (OFF_S0 + 256)
#define OFF_WO   (OFF_B0 + 256)
#define OFF_SOBO (OFF_WO + 256)
#define SMEM_BYTES (OFF_SOBO + 16)

__device__ __align__(16) uint32_t g_wfrag[NLAYER * 8 * 4 * 32 * 4];

static __device__ __forceinline__ float lrelu(float t) { return fmaxf(t, NEG * t); }

static __device__ __forceinline__ uint32_t pack_h2(float a, float b) {
    __half2 h = __floats2half2_rn(a, b);   // a -> low, b -> high
    return *(uint32_t*)&h;
}
static __device__ __forceinline__ float frcp(float x) {
    float r;
    asm("rcp.approx.f32 %0, %1;" : "=f"(r) : "f"(x));
    return r;
}
static __device__ __forceinline__ void mma_f16(float* c, const uint32_t* a,
                                               uint32_t b0, uint32_t b1) {
    asm volatile(
        "mma.sync.aligned.m16n8k16.row.col.f32.f16.f16.f32 "
        "{%0,%1,%2,%3}, {%4,%5,%6,%7}, {%8,%9}, {%0,%1,%2,%3};"
        : "+f"(c[0]), "+f"(c[1]), "+f"(c[2]), "+f"(c[3])
        : "r"(a[0]), "r"(a[1]), "r"(a[2]), "r"(a[3]), "r"(b0), "r"(b1));
}

// ---------------- prep: (W * diag(s)) -> fp16 hi/lo digits, B-fragment order ----------------
__global__ void prep_weights(const float* __restrict__ wh, const float* __restrict__ sh) {
    int t = blockIdx.x * blockDim.x + threadIdx.x;
    if (t >= NLAYER * 8 * 4 * 32) return;
    int lane = t & 31;
    int kt = (t >> 5) & 3;
    int nt = (t >> 7) & 7;
    int l = t >> 10;
    int k0 = kt * 16 + (lane & 3) * 2;
    int nn = nt * 8 + (lane >> 2);
    const float* W = wh + l * 4096;       // W[k][n] row-major
    float sv = sh[l * 64 + nn];
    float w0 = W[k0 * 64 + nn] * sv;
    float w1 = W[(k0 + 1) * 64 + nn] * sv;
    float w2 = W[(k0 + 8) * 64 + nn] * sv;
    float w3 = W[(k0 + 9) * 64 + nn] * sv;

    __half h0 = __float2half_rn(w0), h1 = __float2half_rn(w1);
    __half h2 = __float2half_rn(w2), h3 = __float2half_rn(w3);
    float l0 = w0 - __half2float(h0), l1 = w1 - __half2float(h1);
    float l2 = w2 - __half2float(h2), l3 = w3 - __half2float(h3);

    uint4 o;
    __half2 p01 = __halves2half2(h0, h1);
    __half2 p23 = __halves2half2(h2, h3);
    o.x = *(uint32_t*)&p01;
    o.y = *(uint32_t*)&p23;
    o.z = pack_h2(l0, l1);
    o.w = pack_h2(l2, l3);
    ((uint4*)g_wfrag)[t] = o;
}

// ---------------- device helpers ----------------
// quantize one chain's 32 post-activation values -> fp16 A fragments + scales
static __device__ __forceinline__ void quantize_chain(
    const float (&o)[8][4], float& r0, float& r1,
    uint32_t (&A)[4][4], unsigned rmask)
{
    float p[8], q[8];
#pragma unroll
    for (int nt = 0; nt < 8; nt++) {
        p[nt] = fmaxf(fabsf(o[nt][0]), fabsf(o[nt][1]));
        q[nt] = fmaxf(fabsf(o[nt][2]), fabsf(o[nt][3]));
    }
    float m0 = fmaxf(fmaxf(fmaxf(p[0], p[1]), fmaxf(p[2], p[3])),
                     fmaxf(fmaxf(p[4], p[5]), fmaxf(p[6], p[7])));
    float m1 = fmaxf(fmaxf(fmaxf(q[0], q[1]), fmaxf(q[2], q[3])),
                     fmaxf(fmaxf(q[4], q[5]), fmaxf(q[6], q[7])));
    m0 = fmaxf(m0, 1e-30f);
    m1 = fmaxf(m1, 1e-30f);
    // positive fp32 bitpatterns are order-isomorphic to u32 -> REDUX over 4-lane group
    m0 = __uint_as_float(__reduce_max_sync(rmask, __float_as_uint(m0)));
    m1 = __uint_as_float(__reduce_max_sync(rmask, __float_as_uint(m1)));
    float inv0 = frcp(m0), inv1 = frcp(m1);
    r0 = m0;
    r1 = m1;
#pragma unroll
    for (int kt = 0; kt < 4; kt++) {
        A[kt][0] = pack_h2(o[2*kt][0]   * inv0, o[2*kt][1]   * inv0);
        A[kt][1] = pack_h2(o[2*kt][2]   * inv1, o[2*kt][3]   * inv1);
        A[kt][2] = pack_h2(o[2*kt+1][0] * inv0, o[2*kt+1][1] * inv0);
        A[kt][3] = pack_h2(o[2*kt+1][2] * inv1, o[2*kt+1][3] * inv1);
    }
}

// hidden-layer epilogue: dequant (scale r; s pre-folded into W) + bias + lrelu + quantize
static __device__ __forceinline__ void epi_full(
    const float (&acc)[8][4], float& r0, float& r1,
    const float* bl, int cb, uint32_t (&A)[4][4], unsigned rmask)
{
    const float R0 = r0, R1 = r1;
    float o[8][4];
#pragma unroll
    for (int nt = 0; nt < 8; nt++) {
        float2 bv = *(const float2*)(bl + nt * 8 + cb);
        float t0 = fmaf(acc[nt][0], R0, bv.x);
        float t1 = fmaf(acc[nt][1], R0, bv.y);
        float t2 = fmaf(acc[nt][2], R1, bv.x);
        float t3 = fmaf(acc[nt][3], R1, bv.y);
        o[nt][0] = lrelu(t0);
        o[nt][1] = lrelu(t1);
        o[nt][2] = lrelu(t2);
        o[nt][3] = lrelu(t3);
    }
    quantize_chain(o, r0, r1, A, rmask);
}

// one chain's MMA for one layer: zero acc, 4 k-tiles x 2 passes (Whi, Wlo)
static __device__ __forceinline__ void mma_block(
    const uint4* wl, const uint32_t (&A)[4][4], float (&acc)[8][4])
{
#pragma unroll
    for (int nt = 0; nt < 8; nt++)
#pragma unroll
        for (int e = 0; e < 4; e++) acc[nt][e] = 0.f;
#pragma unroll
    for (int kt = 0; kt < 4; kt++) {
        uint4 wf[8];
#pragma unroll
        for (int nt = 0; nt < 8; nt++) wf[nt] = wl[(nt * 4 + kt) * 32];
#pragma unroll
        for (int nt = 0; nt < 8; nt++) mma_f16(acc[nt], A[kt], wf[nt].x, wf[nt].y);
#pragma unroll
        for (int nt = 0; nt < 8; nt++) mma_f16(acc[nt], A[kt], wf[nt].z, wf[nt].w);
    }
}

// output epilogue: dequant + bias + lrelu, dot wo, 4-lane reduce, store
static __device__ __forceinline__ void out_epi(
    const float (&acc)[8][4], float r0, float r1,
    const float* bl, const float* wo_sh, int cb,
    float so_v, float bo_v, float* __restrict__ out,
    long long ri0, long long ri1, int n, int tig)
{
    float d0 = 0.f, d1 = 0.f;
#pragma unroll
    for (int nt = 0; nt < 8; nt++) {
        float2 bv = *(const float2*)(bl + nt * 8 + cb);
        float2 wv = *(const float2*)(wo_sh + nt * 8 + cb);
        float t0 = fmaf(acc[nt][0], r0, bv.x);
        float t1 = fmaf(acc[nt][1], r0, bv.y);
        float t2 = fmaf(acc[nt][2], r1, bv.x);
        float t3 = fmaf(acc[nt][3], r1, bv.y);
        d0 = fmaf(lrelu(t0), wv.x, d0);
        d0 = fmaf(lrelu(t1), wv.y, d0);
        d1 = fmaf(lrelu(t2), wv.x, d1);
        d1 = fmaf(lrelu(t3), wv.y, d1);
    }
    d0 += __shfl_xor_sync(0xffffffffu, d0, 1);
    d0 += __shfl_xor_sync(0xffffffffu, d0, 2);
    d1 += __shfl_xor_sync(0xffffffffu, d1, 1);
    d1 += __shfl_xor_sync(0xffffffffu, d1, 2);
    if (tig == 0) {
        if (ri0 < n) out[ri0] = fmaf(d0, so_v, bo_v);
        if (ri1 < n) out[ri1] = fmaf(d1, so_v, bo_v);
    }
}

__global__ __launch_bounds__(NT, 1)
void implicit_mlp_f16(const float* __restrict__ points,
                      const float* __restrict__ w0,
                      const float* __restrict__ s0,
                      const float* __restrict__ b0,
                      const float* __restrict__ bh,
                      const float* __restrict__ wo,
                      const float* __restrict__ so,
                      const float* __restrict__ bo,
                      float* __restrict__ out,
                      int n, int ntiles)
{
    extern __shared__ __align__(16) unsigned char smem[];

    const int tid = threadIdx.x;
    const int wid = tid >> 5;
    const int lane = tid & 31;
    const int tig = lane & 3;
    const int grp = lane >> 2;
    const int cb = tig * 2;
    const unsigned rmask = 0xFu << (lane & ~3);

    {
        const uint4* gsrc = (const uint4*)g_wfrag;
        uint4* gdst = (uint4*)(smem + OFF_WF);
        for (int i = tid; i < WF_BYTES / 16; i += NT) gdst[i] = gsrc[i];
        float* d;
        d = (float*)(smem + OFF_BH); for (int i = tid; i < 384; i += NT) d[i] = bh[i];
        d = (float*)(smem + OFF_W0); for (int i = tid; i < 192; i += NT) d[i] = w0[i];
        d = (float*)(smem + OFF_S0); if (tid < 64) d[tid] = s0[tid];
        d = (float*)(smem + OFF_B0); if (tid < 64) d[tid] = b0[tid];
        d = (float*)(smem + OFF_WO); if (tid < 64) d[tid] = wo[tid];
        if (tid == 0) {
            ((float*)(smem + OFF_SOBO))[0] = so[0];
            ((float*)(smem + OFF_SOBO))[1] = bo[0];
        }
    }
    __syncthreads();

    const float* bh0    = (const float*)(smem + OFF_BH);
    const float* shm_w0 = (const float*)(smem + OFF_W0);
    const float* shm_s0 = (const float*)(smem + OFF_S0);
    const float* shm_b0 = (const float*)(smem + OFF_B0);
    const float* shm_wo = (const float*)(smem + OFF_WO);
    const float so_v = ((const float*)(smem + OFF_SOBO))[0];
    const float bo_v = ((const float*)(smem + OFF_SOBO))[1];
    const uint4* wfp = (const uint4*)(smem + OFF_WF) + lane;

    for (int tile = blockIdx.x; tile < ntiles; tile += gridDim.x) {
        const long long rowbase = (long long)tile * TILE_M + wid * 32;
        const long long ra0 = rowbase + grp,      ra1 = ra0 + 8;   // chain A rows
        const long long rb0 = rowbase + 16 + grp, rb1 = rb0 + 8;   // chain B rows

        float accA[8][4], accB[8][4];
        uint32_t Af[4][4], Bf[4][4];
        float rA0, rA1, rB0, rB1;

        // ---- layer 0 (K=3) scalar: post-activation outputs into accA/accB ----
        {
            float ax = 0.f, ay = 0.f, az = 0.f, bx = 0.f, by = 0.f, bz = 0.f;
            float cx = 0.f, cy = 0.f, cz = 0.f, dx = 0.f, dy = 0.f, dz = 0.f;
            if (ra0 < n) { ax = points[ra0*3+0]; ay = points[ra0*3+1]; az = points[ra0*3+2]; }
            if (ra1 < n) { bx = points[ra1*3+0]; by = points[ra1*3+1]; bz = points[ra1*3+2]; }
            if (rb0 < n) { cx = points[rb0*3+0]; cy = points[rb0*3+1]; cz = points[rb0*3+2]; }
            if (rb1 < n) { dx = points[rb1*3+0]; dy = points[rb1*3+1]; dz = points[rb1*3+2]; }
#pragma unroll
            for (int nt = 0; nt < 8; nt++) {
#pragma unroll
                for (int j = 0; j < 2; j++) {
                    int c = nt * 8 + cb + j;
                    float wa = shm_w0[c], wb = shm_w0[64 + c], wc = shm_w0[128 + c];
                    float sv = shm_s0[c], bv = shm_b0[c];
                    accA[nt][j]     = lrelu(fmaf(fmaf(ax, wa, fmaf(ay, wb, az * wc)), sv, bv));
                    accA[nt][2 + j] = lrelu(fmaf(fmaf(bx, wa, fmaf(by, wb, bz * wc)), sv, bv));
                    accB[nt][j]     = lrelu(fmaf(fmaf(cx, wa, fmaf(cy, wb, cz * wc)), sv, bv));
                    accB[nt][2 + j] = lrelu(fmaf(fmaf(dx, wa, fmaf(dy, wb, dz * wc)), sv, bv));
                }
            }
        }
        quantize_chain(accA, rA0, rA1, Af, rmask);

        // ---- L = 0 (peeled: chain B epilogue is quantize-only) ----
        mma_block(wfp, Af, accA);
        quantize_chain(accB, rB0, rB1, Bf, rmask);
        mma_block(wfp, Bf, accB);
        epi_full(accA, rA0, rA1, bh0, cb, Af, rmask);

        // ---- L = 1..4 pipelined: mmaA -> epiB(prev) -> mmaB -> epiA ----
#pragma unroll
        for (int L = 1; L <= 4; L++) {
            const uint4* wl = wfp + L * 1024;
            mma_block(wl, Af, accA);
            epi_full(accB, rB0, rB1, bh0 + (L - 1) * 64, cb, Bf, rmask);
            mma_block(wl, Bf, accB);
            epi_full(accA, rA0, rA1, bh0 + L * 64, cb, Af, rmask);
        }

        // ---- L = 5 (peeled: chain A goes straight to output epilogue) ----
        {
            const uint4* wl = wfp + 5 * 1024;
            mma_block(wl, Af, accA);
            epi_full(accB, rB0, rB1, bh0 + 4 * 64, cb, Bf, rmask);
            mma_block(wl, Bf, accB);
            out_epi(accA, rA0, rA1, bh0 + 5 * 64, shm_wo, cb, so_v, bo_v, out, ra0, ra1, n, tig);
            out_epi(accB, rB0, rB1, bh0 + 5 * 64, shm_wo, cb, so_v, bo_v, out, rb0, rb1, n, tig);
        }
    }
}

extern "C" void kernel_launch(void* const* d_in, const int* in_sizes, int n_in,
                              void* d_out, int out_size)
{
    const float* points = (const float*)d_in[0];
    const float* w0     = (const float*)d_in[1];
    const float* s0     = (const float*)d_in[2];
    const float* b0     = (const float*)d_in[3];
    const float* wh     = (const float*)d_in[4];
    const float* sh     = (const float*)d_in[5];
    const float* bh     = (const float*)d_in[6];
    const float* wo     = (const float*)d_in[7];
    const float* so     = (const float*)d_in[8];
    const float* bo     = (const float*)d_in[9];
    float* out = (float*)d_out;

    const int n = in_sizes[0] / 3;
    const int ntiles = (n + TILE_M - 1) / TILE_M;

    prep_weights<<<(NLAYER * 8 * 4 * 32 + 255) / 256, 256>>>(wh, sh);

    int sms = 148;
    cudaDeviceGetAttribute(&sms, cudaDevAttrMultiProcessorCount, 0);
    cudaFuncSetAttribute(implicit_mlp_f16,
                         cudaFuncAttributeMaxDynamicSharedMemorySize, SMEM_BYTES);
    int grid = sms < ntiles ? sms : ntiles;

    implicit_mlp_f16<<<grid, NT, SMEM_BYTES>>>(
        points, w0, s0, b0, bh, wo, so, bo, out, n, ntiles);
}

// round 11
// speedup vs baseline: 1.3796x; 1.3796x over previous
#include <cuda_runtime.h>
#include <cuda_fp16.h>
#include <cstdint>

// ImplicitFunction: fp16 m16n8k16 mma.sync, 2-term static weight split
// (W*s = Whi + Wlo), dynamically range-scaled fp16 activations.
// Round-11: single chain per warp (r9 skeleton, low regs) at 16 rows/warp
// with 2 CTAs/SM -> 4 warps/SMSP. Epilogue latency is hidden by OTHER
// warps' HMMA bursts (no mainloop syncs; warps drift freely), instead of
// round 10's register-doubling intra-warp dual chains.
// Keeps r10's cheap epilogue: s folded into weights, tree-max + redux.sync
// + rcp.approx quantize.

#define NT 256
#define TILE_M 128          // 8 warps * 16 rows; 2 CTAs per SM
#define NEG 0.2f
#define NLAYER 6

#define OFF_WF   0
#define WF_BYTES (NLAYER * 8 * 4 * 32 * 16)   // [l][nt][kt][lane]{hi0,hi1,lo0,lo1}
#define OFF_BH   (OFF_WF + WF_BYTES)
#define OFF_W0   (OFF_BH + 1536)
#define OFF_S0   (OFF_W0 + 768)
#define OFF_B0   (OFF_S0 + 256)
#define OFF_WO   (OFF_B0 + 256)
#define OFF_SOBO (OFF_WO + 256)
#define SMEM_BYTES (OFF_SOBO + 16)

__device__ __align__(16) uint32_t g_wfrag[NLAYER * 8 * 4 * 32 * 4];

static __device__ __forceinline__ float lrelu(float t) { return fmaxf(t, NEG * t); }

static __device__ __forceinline__ uint32_t pack_h2(float a, float b) {
    __half2 h = __floats2half2_rn(a, b);   // a -> low, b -> high
    return *(uint32_t*)&h;
}
static __device__ __forceinline__ float frcp(float x) {
    float r;
    asm("rcp.approx.f32 %0, %1;" : "=f"(r) : "f"(x));
    return r;
}
static __device__ __forceinline__ void mma_f16(float* c, const uint32_t* a,
                                               uint32_t b0, uint32_t b1) {
    asm volatile(
        "mma.sync.aligned.m16n8k16.row.col.f32.f16.f16.f32 "
        "{%0,%1,%2,%3}, {%4,%5,%6,%7}, {%8,%9}, {%0,%1,%2,%3};"
        : "+f"(c[0]), "+f"(c[1]), "+f"(c[2]), "+f"(c[3])
        : "r"(a[0]), "r"(a[1]), "r"(a[2]), "r"(a[3]), "r"(b0), "r"(b1));
}

// ---------------- prep: (W * diag(s)) -> fp16 hi/lo digits, B-fragment order ----------------
__global__ void prep_weights(const float* __restrict__ wh, const float* __restrict__ sh) {
    int t = blockIdx.x * blockDim.x + threadIdx.x;
    if (t >= NLAYER * 8 * 4 * 32) return;
    int lane = t & 31;
    int kt = (t >> 5) & 3;
    int nt = (t >> 7) & 7;
    int l = t >> 10;
    int k0 = kt * 16 + (lane & 3) * 2;
    int nn = nt * 8 + (lane >> 2);
    const float* W = wh + l * 4096;       // W[k][n] row-major
    float sv = sh[l * 64 + nn];
    float w0 = W[k0 * 64 + nn] * sv;
    float w1 = W[(k0 + 1) * 64 + nn] * sv;
    float w2 = W[(k0 + 8) * 64 + nn] * sv;
    float w3 = W[(k0 + 9) * 64 + nn] * sv;

    __half h0 = __float2half_rn(w0), h1 = __float2half_rn(w1);
    __half h2 = __float2half_rn(w2), h3 = __float2half_rn(w3);
    float l0 = w0 - __half2float(h0), l1 = w1 - __half2float(h1);
    float l2 = w2 - __half2float(h2), l3 = w3 - __half2float(h3);

    uint4 o;
    __half2 p01 = __halves2half2(h0, h1);
    __half2 p23 = __halves2half2(h2, h3);
    o.x = *(uint32_t*)&p01;
    o.y = *(uint32_t*)&p23;
    o.z = pack_h2(l0, l1);
    o.w = pack_h2(l2, l3);
    ((uint4*)g_wfrag)[t] = o;
}

// ---------------- device helpers ----------------
// quantize 32 post-activation values -> fp16 A fragments + per-rowhalf scales
static __device__ __forceinline__ void quantize_chain(
    const float (&o)[8][4], float& r0, float& r1,
    uint32_t (&A)[4][4], unsigned rmask)
{
    float p[8], q[8];
#pragma unroll
    for (int nt = 0; nt < 8; nt++) {
        p[nt] = fmaxf(fabsf(o[nt][0]), fabsf(o[nt][1]));
        q[nt] = fmaxf(fabsf(o[nt][2]), fabsf(o[nt][3]));
    }
    float m0 = fmaxf(fmaxf(fmaxf(p[0], p[1]), fmaxf(p[2], p[3])),
                     fmaxf(fmaxf(p[4], p[5]), fmaxf(p[6], p[7])));
    float m1 = fmaxf(fmaxf(fmaxf(q[0], q[1]), fmaxf(q[2], q[3])),
                     fmaxf(fmaxf(q[4], q[5]), fmaxf(q[6], q[7])));
    m0 = fmaxf(m0, 1e-30f);
    m1 = fmaxf(m1, 1e-30f);
    // positive fp32 bitpatterns are order-isomorphic to u32 -> REDUX over 4-lane group
    m0 = __uint_as_float(__reduce_max_sync(rmask, __float_as_uint(m0)));
    m1 = __uint_as_float(__reduce_max_sync(rmask, __float_as_uint(m1)));
    float inv0 = frcp(m0), inv1 = frcp(m1);
    r0 = m0;
    r1 = m1;
#pragma unroll
    for (int kt = 0; kt < 4; kt++) {
        A[kt][0] = pack_h2(o[2*kt][0]   * inv0, o[2*kt][1]   * inv0);
        A[kt][1] = pack_h2(o[2*kt][2]   * inv1, o[2*kt][3]   * inv1);
        A[kt][2] = pack_h2(o[2*kt+1][0] * inv0, o[2*kt+1][1] * inv0);
        A[kt][3] = pack_h2(o[2*kt+1][2] * inv1, o[2*kt+1][3] * inv1);
    }
}

// hidden-layer epilogue: dequant (s pre-folded into W) + bias + lrelu + quantize
static __device__ __forceinline__ void epi_full(
    const float (&acc)[8][4], float& r0, float& r1,
    const float* bl, int cb, uint32_t (&A)[4][4], unsigned rmask)
{
    const float R0 = r0, R1 = r1;
    float o[8][4];
#pragma unroll
    for (int nt = 0; nt < 8; nt++) {
        float2 bv = *(const float2*)(bl + nt * 8 + cb);
        o[nt][0] = lrelu(fmaf(acc[nt][0], R0, bv.x));
        o[nt][1] = lrelu(fmaf(acc[nt][1], R0, bv.y));
        o[nt][2] = lrelu(fmaf(acc[nt][2], R1, bv.x));
        o[nt][3] = lrelu(fmaf(acc[nt][3], R1, bv.y));
    }
    quantize_chain(o, r0, r1, A, rmask);
}

// one layer's MMA: zero acc, 4 k-tiles x 2 passes (Whi, Wlo)
static __device__ __forceinline__ void mma_block(
    const uint4* wl, const uint32_t (&A)[4][4], float (&acc)[8][4])
{
#pragma unroll
    for (int nt = 0; nt < 8; nt++)
#pragma unroll
        for (int e = 0; e < 4; e++) acc[nt][e] = 0.f;
#pragma unroll
    for (int kt = 0; kt < 4; kt++) {
        uint4 wf[8];
#pragma unroll
        for (int nt = 0; nt < 8; nt++) wf[nt] = wl[(nt * 4 + kt) * 32];
#pragma unroll
        for (int nt = 0; nt < 8; nt++) mma_f16(acc[nt], A[kt], wf[nt].x, wf[nt].y);
#pragma unroll
        for (int nt = 0; nt < 8; nt++) mma_f16(acc[nt], A[kt], wf[nt].z, wf[nt].w);
    }
}

__global__ __launch_bounds__(NT, 2)
void implicit_mlp_f16(const float* __restrict__ points,
                      const float* __restrict__ w0,
                      const float* __restrict__ s0,
                      const float* __restrict__ b0,
                      const float* __restrict__ bh,
                      const float* __restrict__ wo,
                      const float* __restrict__ so,
                      const float* __restrict__ bo,
                      float* __restrict__ out,
                      int n, int ntiles)
{
    extern __shared__ __align__(16) unsigned char smem[];

    const int tid = threadIdx.x;
    const int wid = tid >> 5;
    const int lane = tid & 31;
    const int tig = lane & 3;
    const int grp = lane >> 2;
    const int cb = tig * 2;
    const unsigned rmask = 0xFu << (lane & ~3);

    {
        const uint4* gsrc = (const uint4*)g_wfrag;
        uint4* gdst = (uint4*)(smem + OFF_WF);
        for (int i = tid; i < WF_BYTES / 16; i += NT) gdst[i] = gsrc[i];
        float* d;
        d = (float*)(smem + OFF_BH); for (int i = tid; i < 384; i += NT) d[i] = bh[i];
        d = (float*)(smem + OFF_W0); for (int i = tid; i < 192; i += NT) d[i] = w0[i];
        d = (float*)(smem + OFF_S0); if (tid < 64) d[tid] = s0[tid];
        d = (float*)(smem + OFF_B0); if (tid < 64) d[tid] = b0[tid];
        d = (float*)(smem + OFF_WO); if (tid < 64) d[tid] = wo[tid];
        if (tid == 0) {
            ((float*)(smem + OFF_SOBO))[0] = so[0];
            ((float*)(smem + OFF_SOBO))[1] = bo[0];
        }
    }
    __syncthreads();

    const float* bh0    = (const float*)(smem + OFF_BH);
    const float* shm_w0 = (const float*)(smem + OFF_W0);
    const float* shm_s0 = (const float*)(smem + OFF_S0);
    const float* shm_b0 = (const float*)(smem + OFF_B0);
    const float* shm_wo = (const float*)(smem + OFF_WO);
    const float so_v = ((const float*)(smem + OFF_SOBO))[0];
    const float bo_v = ((const float*)(smem + OFF_SOBO))[1];
    const uint4* wfp = (const uint4*)(smem + OFF_WF) + lane;

    for (int tile = blockIdx.x; tile < ntiles; tile += gridDim.x) {
        const long long r0 = (long long)tile * TILE_M + wid * 16 + grp;
        const long long r1 = r0 + 8;

        float acc[8][4];
        uint32_t A[4][4];
        float rm0, rm1;

        // ---- layer 0 (K=3) scalar -> post-activation outputs in acc ----
        {
            float ax = 0.f, ay = 0.f, az = 0.f, bx = 0.f, by = 0.f, bz = 0.f;
            if (r0 < n) { ax = points[r0*3+0]; ay = points[r0*3+1]; az = points[r0*3+2]; }
            if (r1 < n) { bx = points[r1*3+0]; by = points[r1*3+1]; bz = points[r1*3+2]; }
#pragma unroll
            for (int nt = 0; nt < 8; nt++) {
#pragma unroll
                for (int j = 0; j < 2; j++) {
                    int c = nt * 8 + cb + j;
                    float wa = shm_w0[c], wb = shm_w0[64 + c], wc = shm_w0[128 + c];
                    float sv = shm_s0[c], bv = shm_b0[c];
                    acc[nt][j]     = lrelu(fmaf(fmaf(ax, wa, fmaf(ay, wb, az * wc)), sv, bv));
                    acc[nt][2 + j] = lrelu(fmaf(fmaf(bx, wa, fmaf(by, wb, bz * wc)), sv, bv));
                }
            }
        }
        quantize_chain(acc, rm0, rm1, A, rmask);

        // ---- 6 hidden layers: mma -> epilogue (other warps hide the latency) ----
#pragma unroll
        for (int l = 0; l < NLAYER; l++) {
            mma_block(wfp + l * 1024, A, acc);
            if (l < NLAYER - 1) {
                epi_full(acc, rm0, rm1, bh0 + l * 64, cb, A, rmask);
            } else {
                // output epilogue: dequant + bias + lrelu, dot wo, reduce, store
                const float* bl = bh0 + 5 * 64;
                float d0 = 0.f, d1 = 0.f;
#pragma unroll
                for (int nt = 0; nt < 8; nt++) {
                    float2 bv = *(const float2*)(bl + nt * 8 + cb);
                    float2 wv = *(const float2*)(shm_wo + nt * 8 + cb);
                    d0 = fmaf(lrelu(fmaf(acc[nt][0], rm0, bv.x)), wv.x, d0);
                    d0 = fmaf(lrelu(fmaf(acc[nt][1], rm0, bv.y)), wv.y, d0);
                    d1 = fmaf(lrelu(fmaf(acc[nt][2], rm1, bv.x)), wv.x, d1);
                    d1 = fmaf(lrelu(fmaf(acc[nt][3], rm1, bv.y)), wv.y, d1);
                }
                d0 += __shfl_xor_sync(0xffffffffu, d0, 1);
                d0 += __shfl_xor_sync(0xffffffffu, d0, 2);
                d1 += __shfl_xor_sync(0xffffffffu, d1, 1);
                d1 += __shfl_xor_sync(0xffffffffu, d1, 2);
                if (tig == 0) {
                    if (r0 < n) out[r0] = fmaf(d0, so_v, bo_v);
                    if (r1 < n) out[r1] = fmaf(d1, so_v, bo_v);
                }
            }
        }
    }
}

extern "C" void kernel_launch(void* const* d_in, const int* in_sizes, int n_in,
                              void* d_out, int out_size)
{
    const float* points = (const float*)d_in[0];
    const float* w0     = (const float*)d_in[1];
    const float* s0     = (const float*)d_in[2];
    const float* b0     = (const float*)d_in[3];
    const float* wh     = (const float*)d_in[4];
    const float* sh     = (const float*)d_in[5];
    const float* bh     = (const float*)d_in[6];
    const float* wo     = (const float*)d_in[7];
    const float* so     = (const float*)d_in[8];
    const float* bo     = (const float*)d_in[9];
    float* out = (float*)d_out;

    const int n = in_sizes[0] / 3;
    const int ntiles = (n + TILE_M - 1) / TILE_M;

    prep_weights<<<(NLAYER * 8 * 4 * 32 + 255) / 256, 256>>>(wh, sh);

    int sms = 148;
    cudaDeviceGetAttribute(&sms, cudaDevAttrMultiProcessorCount, 0);
    cudaFuncSetAttribute(implicit_mlp_f16,
                         cudaFuncAttributeMaxDynamicSharedMemorySize, SMEM_BYTES);
    int grid = 2 * sms < ntiles ? 2 * sms : ntiles;

    implicit_mlp_f16<<<grid, NT, SMEM_BYTES>>>(
        points, w0, s0, b0, bh, wo, so, bo, out, n, ntiles);
}